// round 1
// baseline (speedup 1.0000x reference)
#include <cuda_runtime.h>
#include <math.h>
#include <stdint.h>

#define W_WIN 4096
#define KTOK  32
#define CDIM  256
#define HEADS 8
#define DHEAD 32
#define NTOK  (W_WIN * KTOK)
#define KC    27
#define SDIM  33
#define EPS   1e-5f

// Scratch: data + CPE (post-batchnorm residual add), laid out [NTOK][CDIM]
__device__ float g_xpost[(size_t)NTOK * CDIM];

// ---------------------------------------------------------------------------
// Kernel 1: CPE gather + batchnorm + residual
// one block per token, 256 threads (one per channel)
// ---------------------------------------------------------------------------
__global__ void __launch_bounds__(256) cpe_kernel(
    const float* __restrict__ data,
    const int*   __restrict__ neigh,
    const float* __restrict__ cpe_w,
    const float* __restrict__ bn_gamma,
    const float* __restrict__ bn_beta,
    const float* __restrict__ bn_mean,
    const float* __restrict__ bn_var)
{
    int n = blockIdx.x;
    int c = threadIdx.x;
    __shared__ int nb[KC];
    if (c < KC) nb[c] = neigh[(size_t)n * KC + c];
    __syncthreads();

    float acc = 0.f;
    #pragma unroll
    for (int k = 0; k < KC; k++) {
        acc = fmaf(data[(size_t)nb[k] * CDIM + c], cpe_w[k * CDIM + c], acc);
    }
    float cpe = (acc - bn_mean[c]) * rsqrtf(bn_var[c] + EPS) * bn_gamma[c] + bn_beta[c];
    g_xpost[(size_t)n * CDIM + c] = data[(size_t)n * CDIM + c] + cpe;
}

// ---------------------------------------------------------------------------
// Fused per-window transformer block
// ---------------------------------------------------------------------------

__device__ __forceinline__ float gelu_tanh(float x) {
    float x3 = x * x * x;
    float t = tanhf(0.7978845608028654f * (x + 0.044715f * x3));
    return 0.5f * x * (1.f + t);
}

// LayerNorm over rows of a 33 x 256 smem tile: in -> out. 8 warps, warp per row.
__device__ __forceinline__ void layernorm_rows(
    const float* __restrict__ in, float* __restrict__ out,
    const float* __restrict__ g, const float* __restrict__ b, int tid)
{
    int warp = tid >> 5, lane = tid & 31;
    for (int r = warp; r < SDIM; r += 8) {
        const float* row = in + r * CDIM;
        float s = 0.f, s2 = 0.f;
        #pragma unroll
        for (int i = 0; i < 8; i++) {
            float v = row[lane + i * 32];
            s += v; s2 = fmaf(v, v, s2);
        }
        #pragma unroll
        for (int off = 16; off; off >>= 1) {
            s  += __shfl_xor_sync(0xffffffffu, s, off);
            s2 += __shfl_xor_sync(0xffffffffu, s2, off);
        }
        float mu  = s * (1.f / CDIM);
        float var = s2 * (1.f / CDIM) - mu * mu;
        float rs  = rsqrtf(var + EPS);
        #pragma unroll
        for (int i = 0; i < 8; i++) {
            int c = lane + i * 32;
            out[r * CDIM + c] = (row[c] - mu) * rs * g[c] + b[c];
        }
    }
}

// One output column j of a [33 x KDIM] @ [KDIM x NCOLS] GEMM.
// A in smem (row stride KDIM), W in global row-major. acc[33] in registers.
// Weights read exactly once per block; activations via broadcast LDS.128.
template <int KDIM, int NCOLS>
__device__ __forceinline__ void gemm_col(
    const float* __restrict__ A, const float* __restrict__ Wt,
    int j, float acc[SDIM])
{
    #pragma unroll
    for (int r = 0; r < SDIM; r++) acc[r] = 0.f;
    for (int k = 0; k < KDIM; k += 4) {
        float w0 = Wt[(size_t)(k + 0) * NCOLS + j];
        float w1 = Wt[(size_t)(k + 1) * NCOLS + j];
        float w2 = Wt[(size_t)(k + 2) * NCOLS + j];
        float w3 = Wt[(size_t)(k + 3) * NCOLS + j];
        #pragma unroll
        for (int r = 0; r < SDIM; r++) {
            float4 a = *reinterpret_cast<const float4*>(A + r * KDIM + k);
            acc[r] = fmaf(a.x, w0, acc[r]);
            acc[r] = fmaf(a.y, w1, acc[r]);
            acc[r] = fmaf(a.z, w2, acc[r]);
            acc[r] = fmaf(a.w, w3, acc[r]);
        }
    }
}

// smem layout (floats): sx[33*256] | sh[33*256] | sbig[33*1024]
#define SX_OFF   0
#define SH_OFF   (SDIM * CDIM)
#define SBIG_OFF (2 * SDIM * CDIM)
#define SMEM_FLOATS (2 * SDIM * CDIM + SDIM * 1024)

__global__ void __launch_bounds__(256, 1) window_block_kernel(
    const float* __restrict__ relay,
    const float* __restrict__ norm1_g, const float* __restrict__ norm1_b,
    const float* __restrict__ qkv_w,   const float* __restrict__ qkv_b,
    const float* __restrict__ proj_w,  const float* __restrict__ proj_b,
    const float* __restrict__ norm2_g, const float* __restrict__ norm2_b,
    const float* __restrict__ fc1_w,   const float* __restrict__ fc1_b,
    const float* __restrict__ fc2_w,   const float* __restrict__ fc2_b,
    float* __restrict__ out)
{
    extern __shared__ float smem[];
    float* sx   = smem + SX_OFF;    // residual stream, 33 x 256
    float* sh   = smem + SH_OFF;    // LN output / attn output, 33 x 256
    float* sbig = smem + SBIG_OFF;  // qkv (stride 768) / ffn hidden (stride 1024)

    int w   = blockIdx.x;
    int tid = threadIdx.x;

    // ---- load window: row 0 = relay token, rows 1..32 = tokens ----
    for (int e = tid; e < SDIM * CDIM; e += 256) {
        int r = e >> 8, c = e & 255;
        sx[e] = (r == 0) ? relay[(size_t)w * CDIM + c]
                         : g_xpost[((size_t)w * KTOK + (r - 1)) * CDIM + c];
    }
    __syncthreads();

    // ---- LN1 ----
    layernorm_rows(sx, sh, norm1_g, norm1_b, tid);
    __syncthreads();

    // ---- QKV: [33x256] @ [256x768] -> sbig (stride 768) ----
    for (int it = 0; it < 3; it++) {
        int j = it * 256 + tid;
        float acc[SDIM];
        gemm_col<256, 768>(sh, qkv_w, j, acc);
        float bias = qkv_b[j];
        #pragma unroll
        for (int r = 0; r < SDIM; r++) sbig[r * 768 + j] = acc[r] + bias;
    }
    __syncthreads();

    // ---- attention: unit = (head, query-row), 264 units ----
    const float scale = 0.17677669529663687f;  // 1/sqrt(32)
    for (int u = tid; u < HEADS * SDIM; u += 256) {
        int h = u / SDIM;   // consecutive tid -> same head, consecutive s (broadcast-friendly)
        int s = u % SDIM;
        const float* qrow = sbig + s * 768 + h * DHEAD;
        float q[DHEAD];
        #pragma unroll
        for (int d = 0; d < DHEAD; d++) q[d] = qrow[d] * scale;

        float sc[SDIM];
        float mx = -1e30f;
        #pragma unroll 1
        for (int t = 0; t < SDIM; t++) {
            const float* krow = sbig + t * 768 + CDIM + h * DHEAD;
            float dot = 0.f;
            #pragma unroll
            for (int d = 0; d < DHEAD; d++) dot = fmaf(q[d], krow[d], dot);
            sc[t] = dot;
            mx = fmaxf(mx, dot);
        }
        float ssum = 0.f;
        #pragma unroll
        for (int t = 0; t < SDIM; t++) { sc[t] = expf(sc[t] - mx); ssum += sc[t]; }
        float inv = 1.f / ssum;

        float o[DHEAD];
        #pragma unroll
        for (int d = 0; d < DHEAD; d++) o[d] = 0.f;
        #pragma unroll 1
        for (int t = 0; t < SDIM; t++) {
            const float* vrow = sbig + t * 768 + 2 * CDIM + h * DHEAD;
            float p = sc[t] * inv;
            #pragma unroll
            for (int d = 0; d < DHEAD; d++) o[d] = fmaf(p, vrow[d], o[d]);
        }
        float* orow = sh + s * CDIM + h * DHEAD;  // channel = h*D + d
        #pragma unroll
        for (int d = 0; d < DHEAD; d++) orow[d] = o[d];
    }
    __syncthreads();

    // ---- proj + residual: sx += sh @ proj_w + b ----
    {
        int j = tid;
        float acc[SDIM];
        gemm_col<256, 256>(sh, proj_w, j, acc);
        float bias = proj_b[j];
        #pragma unroll
        for (int r = 0; r < SDIM; r++) sx[r * CDIM + j] += acc[r] + bias;
    }
    __syncthreads();

    // ---- LN2 ----
    layernorm_rows(sx, sh, norm2_g, norm2_b, tid);
    __syncthreads();

    // ---- FC1 + GELU: [33x256]@[256x1024] -> sbig (stride 1024) ----
    for (int it = 0; it < 4; it++) {
        int j = it * 256 + tid;
        float acc[SDIM];
        gemm_col<256, 1024>(sh, fc1_w, j, acc);
        float bias = fc1_b[j];
        #pragma unroll
        for (int r = 0; r < SDIM; r++) sbig[r * 1024 + j] = gelu_tanh(acc[r] + bias);
    }
    __syncthreads();

    // ---- FC2 + residual: sx += sbig @ fc2_w + b ----
    {
        int j = tid;
        float acc[SDIM];
        gemm_col<1024, 256>(sbig, fc2_w, j, acc);
        float bias = fc2_b[j];
        #pragma unroll
        for (int r = 0; r < SDIM; r++) sx[r * CDIM + j] += acc[r] + bias;
    }
    __syncthreads();

    // ---- outputs: data_out = rows 1..32, rt = row 0 appended after data_out ----
    for (int e = tid; e < SDIM * CDIM; e += 256) {
        int r = e >> 8, c = e & 255;
        float v = sx[e];
        if (r == 0)
            out[(size_t)NTOK * CDIM + (size_t)w * CDIM + c] = v;
        else
            out[((size_t)w * KTOK + (r - 1)) * CDIM + c] = v;
    }
}

// ---------------------------------------------------------------------------
extern "C" void kernel_launch(void* const* d_in, const int* in_sizes, int n_in,
                              void* d_out, int out_size)
{
    const float* data     = (const float*)d_in[0];
    const float* relay    = (const float*)d_in[1];
    const int*   neigh    = (const int*)  d_in[2];
    const float* cpe_w    = (const float*)d_in[3];
    const float* bn_gamma = (const float*)d_in[4];
    const float* bn_beta  = (const float*)d_in[5];
    const float* bn_mean  = (const float*)d_in[6];
    const float* bn_var   = (const float*)d_in[7];
    const float* norm1_g  = (const float*)d_in[8];
    const float* norm1_b  = (const float*)d_in[9];
    const float* qkv_w    = (const float*)d_in[10];
    const float* qkv_b    = (const float*)d_in[11];
    const float* proj_w   = (const float*)d_in[12];
    const float* proj_b   = (const float*)d_in[13];
    const float* norm2_g  = (const float*)d_in[14];
    const float* norm2_b  = (const float*)d_in[15];
    const float* fc1_w    = (const float*)d_in[16];
    const float* fc1_b    = (const float*)d_in[17];
    const float* fc2_w    = (const float*)d_in[18];
    const float* fc2_b    = (const float*)d_in[19];
    float* out = (float*)d_out;

    cpe_kernel<<<NTOK, 256>>>(data, neigh, cpe_w, bn_gamma, bn_beta, bn_mean, bn_var);

    static int smem_set = 0;
    size_t smem_bytes = SMEM_FLOATS * sizeof(float);  // 202752 B
    if (!smem_set) {
        cudaFuncSetAttribute(window_block_kernel,
                             cudaFuncAttributeMaxDynamicSharedMemorySize,
                             (int)smem_bytes);
        smem_set = 1;
    }

    window_block_kernel<<<W_WIN, 256, smem_bytes>>>(
        relay, norm1_g, norm1_b, qkv_w, qkv_b, proj_w, proj_b,
        norm2_g, norm2_b, fc1_w, fc1_b, fc2_w, fc2_b, out);
}

// round 2
// speedup vs baseline: 1.0027x; 1.0027x over previous
#include <cuda_runtime.h>
#include <math.h>
#include <stdint.h>

#define W_WIN 4096
#define KTOK  32
#define CDIM  256
#define HEADS 8
#define DHEAD 32
#define NTOK  (W_WIN * KTOK)
#define KC    27
#define SDIM  33
#define EPS   1e-5f

// Scratch: data + CPE (post-batchnorm residual add), laid out [NTOK][CDIM]
__device__ float g_xpost[(size_t)NTOK * CDIM];

// ---------------------------------------------------------------------------
// Kernel 1: CPE gather + batchnorm + residual
// one block per token, 256 threads (one per channel)
// ---------------------------------------------------------------------------
__global__ void __launch_bounds__(256) cpe_kernel(
    const float* __restrict__ data,
    const int*   __restrict__ neigh,
    const float* __restrict__ cpe_w,
    const float* __restrict__ bn_gamma,
    const float* __restrict__ bn_beta,
    const float* __restrict__ bn_mean,
    const float* __restrict__ bn_var)
{
    int n = blockIdx.x;
    int c = threadIdx.x;
    __shared__ int nb[KC];
    if (c < KC) nb[c] = neigh[(size_t)n * KC + c];
    __syncthreads();

    float acc = 0.f;
    #pragma unroll
    for (int k = 0; k < KC; k++) {
        acc = fmaf(data[(size_t)nb[k] * CDIM + c], cpe_w[k * CDIM + c], acc);
    }
    float cpe = (acc - bn_mean[c]) * rsqrtf(bn_var[c] + EPS) * bn_gamma[c] + bn_beta[c];
    g_xpost[(size_t)n * CDIM + c] = data[(size_t)n * CDIM + c] + cpe;
}

// ---------------------------------------------------------------------------
// Fused per-window transformer block
// ---------------------------------------------------------------------------

__device__ __forceinline__ float gelu_tanh(float x) {
    float x3 = x * x * x;
    float t = tanhf(0.7978845608028654f * (x + 0.044715f * x3));
    return 0.5f * x * (1.f + t);
}

// LayerNorm over rows of a 33 x 256 smem tile: in -> out. 8 warps, warp per row.
__device__ __forceinline__ void layernorm_rows(
    const float* __restrict__ in, float* __restrict__ out,
    const float* __restrict__ g, const float* __restrict__ b, int tid)
{
    int warp = tid >> 5, lane = tid & 31;
    for (int r = warp; r < SDIM; r += 8) {
        const float* row = in + r * CDIM;
        float s = 0.f, s2 = 0.f;
        #pragma unroll
        for (int i = 0; i < 8; i++) {
            float v = row[lane + i * 32];
            s += v; s2 = fmaf(v, v, s2);
        }
        #pragma unroll
        for (int off = 16; off; off >>= 1) {
            s  += __shfl_xor_sync(0xffffffffu, s, off);
            s2 += __shfl_xor_sync(0xffffffffu, s2, off);
        }
        float mu  = s * (1.f / CDIM);
        float var = s2 * (1.f / CDIM) - mu * mu;
        float rs  = rsqrtf(var + EPS);
        #pragma unroll
        for (int i = 0; i < 8; i++) {
            int c = lane + i * 32;
            out[r * CDIM + c] = (row[c] - mu) * rs * g[c] + b[c];
        }
    }
}

// One output column j of a [33 x KDIM] @ [KDIM x NCOLS] GEMM.
// A in smem (row stride KDIM), W in global row-major. acc[33] in registers.
// Weights read exactly once per block; activations via broadcast LDS.128.
template <int KDIM, int NCOLS>
__device__ __forceinline__ void gemm_col(
    const float* __restrict__ A, const float* __restrict__ Wt,
    int j, float acc[SDIM])
{
    #pragma unroll
    for (int r = 0; r < SDIM; r++) acc[r] = 0.f;
    for (int k = 0; k < KDIM; k += 4) {
        float w0 = Wt[(size_t)(k + 0) * NCOLS + j];
        float w1 = Wt[(size_t)(k + 1) * NCOLS + j];
        float w2 = Wt[(size_t)(k + 2) * NCOLS + j];
        float w3 = Wt[(size_t)(k + 3) * NCOLS + j];
        #pragma unroll
        for (int r = 0; r < SDIM; r++) {
            float4 a = *reinterpret_cast<const float4*>(A + r * KDIM + k);
            acc[r] = fmaf(a.x, w0, acc[r]);
            acc[r] = fmaf(a.y, w1, acc[r]);
            acc[r] = fmaf(a.z, w2, acc[r]);
            acc[r] = fmaf(a.w, w3, acc[r]);
        }
    }
}

// smem layout (floats): sx[33*256] | sh[33*256] | sbig[33*1024]
#define SX_OFF   0
#define SH_OFF   (SDIM * CDIM)
#define SBIG_OFF (2 * SDIM * CDIM)
#define SMEM_FLOATS (2 * SDIM * CDIM + SDIM * 1024)

__global__ void __launch_bounds__(256, 1) window_block_kernel(
    const float* __restrict__ relay,
    const float* __restrict__ norm1_g, const float* __restrict__ norm1_b,
    const float* __restrict__ qkv_w,   const float* __restrict__ qkv_b,
    const float* __restrict__ proj_w,  const float* __restrict__ proj_b,
    const float* __restrict__ norm2_g, const float* __restrict__ norm2_b,
    const float* __restrict__ fc1_w,   const float* __restrict__ fc1_b,
    const float* __restrict__ fc2_w,   const float* __restrict__ fc2_b,
    float* __restrict__ out)
{
    extern __shared__ float smem[];
    float* sx   = smem + SX_OFF;    // residual stream, 33 x 256
    float* sh   = smem + SH_OFF;    // LN output / attn output, 33 x 256
    float* sbig = smem + SBIG_OFF;  // qkv (stride 768) / ffn hidden (stride 1024)

    int w   = blockIdx.x;
    int tid = threadIdx.x;

    // ---- load window: row 0 = relay token, rows 1..32 = tokens ----
    for (int e = tid; e < SDIM * CDIM; e += 256) {
        int r = e >> 8, c = e & 255;
        sx[e] = (r == 0) ? relay[(size_t)w * CDIM + c]
                         : g_xpost[((size_t)w * KTOK + (r - 1)) * CDIM + c];
    }
    __syncthreads();

    // ---- LN1 ----
    layernorm_rows(sx, sh, norm1_g, norm1_b, tid);
    __syncthreads();

    // ---- QKV: [33x256] @ [256x768] -> sbig (stride 768) ----
    for (int it = 0; it < 3; it++) {
        int j = it * 256 + tid;
        float acc[SDIM];
        gemm_col<256, 768>(sh, qkv_w, j, acc);
        float bias = qkv_b[j];
        #pragma unroll
        for (int r = 0; r < SDIM; r++) sbig[r * 768 + j] = acc[r] + bias;
    }
    __syncthreads();

    // ---- attention: unit = (head, query-row), 264 units ----
    const float scale = 0.17677669529663687f;  // 1/sqrt(32)
    for (int u = tid; u < HEADS * SDIM; u += 256) {
        int h = u / SDIM;   // consecutive tid -> same head, consecutive s (broadcast-friendly)
        int s = u % SDIM;
        const float* qrow = sbig + s * 768 + h * DHEAD;
        float q[DHEAD];
        #pragma unroll
        for (int d = 0; d < DHEAD; d++) q[d] = qrow[d] * scale;

        float sc[SDIM];
        float mx = -1e30f;
        #pragma unroll 1
        for (int t = 0; t < SDIM; t++) {
            const float* krow = sbig + t * 768 + CDIM + h * DHEAD;
            float dot = 0.f;
            #pragma unroll
            for (int d = 0; d < DHEAD; d++) dot = fmaf(q[d], krow[d], dot);
            sc[t] = dot;
            mx = fmaxf(mx, dot);
        }
        float ssum = 0.f;
        #pragma unroll
        for (int t = 0; t < SDIM; t++) { sc[t] = expf(sc[t] - mx); ssum += sc[t]; }
        float inv = 1.f / ssum;

        float o[DHEAD];
        #pragma unroll
        for (int d = 0; d < DHEAD; d++) o[d] = 0.f;
        #pragma unroll 1
        for (int t = 0; t < SDIM; t++) {
            const float* vrow = sbig + t * 768 + 2 * CDIM + h * DHEAD;
            float p = sc[t] * inv;
            #pragma unroll
            for (int d = 0; d < DHEAD; d++) o[d] = fmaf(p, vrow[d], o[d]);
        }
        float* orow = sh + s * CDIM + h * DHEAD;  // channel = h*D + d
        #pragma unroll
        for (int d = 0; d < DHEAD; d++) orow[d] = o[d];
    }
    __syncthreads();

    // ---- proj + residual: sx += sh @ proj_w + b ----
    {
        int j = tid;
        float acc[SDIM];
        gemm_col<256, 256>(sh, proj_w, j, acc);
        float bias = proj_b[j];
        #pragma unroll
        for (int r = 0; r < SDIM; r++) sx[r * CDIM + j] += acc[r] + bias;
    }
    __syncthreads();

    // ---- LN2 ----
    layernorm_rows(sx, sh, norm2_g, norm2_b, tid);
    __syncthreads();

    // ---- FC1 + GELU: [33x256]@[256x1024] -> sbig (stride 1024) ----
    for (int it = 0; it < 4; it++) {
        int j = it * 256 + tid;
        float acc[SDIM];
        gemm_col<256, 1024>(sh, fc1_w, j, acc);
        float bias = fc1_b[j];
        #pragma unroll
        for (int r = 0; r < SDIM; r++) sbig[r * 1024 + j] = gelu_tanh(acc[r] + bias);
    }
    __syncthreads();

    // ---- FC2 + residual: sx += sbig @ fc2_w + b ----
    {
        int j = tid;
        float acc[SDIM];
        gemm_col<1024, 256>(sbig, fc2_w, j, acc);
        float bias = fc2_b[j];
        #pragma unroll
        for (int r = 0; r < SDIM; r++) sx[r * CDIM + j] += acc[r] + bias;
    }
    __syncthreads();

    // ---- outputs: data_out = rows 1..32, rt = row 0 appended after data_out ----
    for (int e = tid; e < SDIM * CDIM; e += 256) {
        int r = e >> 8, c = e & 255;
        float v = sx[e];
        if (r == 0)
            out[(size_t)NTOK * CDIM + (size_t)w * CDIM + c] = v;
        else
            out[((size_t)w * KTOK + (r - 1)) * CDIM + c] = v;
    }
}

// ---------------------------------------------------------------------------
extern "C" void kernel_launch(void* const* d_in, const int* in_sizes, int n_in,
                              void* d_out, int out_size)
{
    const float* data     = (const float*)d_in[0];
    const float* relay    = (const float*)d_in[1];
    const int*   neigh    = (const int*)  d_in[2];
    const float* cpe_w    = (const float*)d_in[3];
    const float* bn_gamma = (const float*)d_in[4];
    const float* bn_beta  = (const float*)d_in[5];
    const float* bn_mean  = (const float*)d_in[6];
    const float* bn_var   = (const float*)d_in[7];
    const float* norm1_g  = (const float*)d_in[8];
    const float* norm1_b  = (const float*)d_in[9];
    const float* qkv_w    = (const float*)d_in[10];
    const float* qkv_b    = (const float*)d_in[11];
    const float* proj_w   = (const float*)d_in[12];
    const float* proj_b   = (const float*)d_in[13];
    const float* norm2_g  = (const float*)d_in[14];
    const float* norm2_b  = (const float*)d_in[15];
    const float* fc1_w    = (const float*)d_in[16];
    const float* fc1_b    = (const float*)d_in[17];
    const float* fc2_w    = (const float*)d_in[18];
    const float* fc2_b    = (const float*)d_in[19];
    float* out = (float*)d_out;

    cpe_kernel<<<NTOK, 256>>>(data, neigh, cpe_w, bn_gamma, bn_beta, bn_mean, bn_var);

    static int smem_set = 0;
    size_t smem_bytes = SMEM_FLOATS * sizeof(float);  // 202752 B
    if (!smem_set) {
        cudaFuncSetAttribute(window_block_kernel,
                             cudaFuncAttributeMaxDynamicSharedMemorySize,
                             (int)smem_bytes);
        smem_set = 1;
    }

    window_block_kernel<<<W_WIN, 256, smem_bytes>>>(
        relay, norm1_g, norm1_b, qkv_w, qkv_b, proj_w, proj_b,
        norm2_g, norm2_b, fc1_w, fc1_b, fc2_w, fc2_b, out);
}

// round 4
// speedup vs baseline: 3.7337x; 3.7236x over previous
#include <cuda_runtime.h>
#include <math.h>
#include <stdint.h>

#define W_WIN 4096
#define KTOK  32
#define CDIM  256
#define HEADS 8
#define DHEAD 32
#define NTOK  (W_WIN * KTOK)
#define KC    27
#define SDIM  33
#define RTOT  (W_WIN * SDIM)
#define EPS   1e-5f

// ---------------- device scratch ----------------
__device__ float g_xpost[(size_t)NTOK * CDIM];
__device__ float g_x   [(size_t)RTOT * CDIM];
__device__ float g_x2  [(size_t)RTOT * CDIM];
__device__ float g_h   [(size_t)RTOT * CDIM];
__device__ float g_h2  [(size_t)RTOT * CDIM];
__device__ float g_qkv [(size_t)RTOT * 3 * CDIM];
__device__ float g_attn[(size_t)RTOT * CDIM];
__device__ float g_f1  [(size_t)RTOT * 1024];
__device__ float g_wq[768 * 256];
__device__ float g_wp[256 * 256];
__device__ float g_w1[1024 * 256];
__device__ float g_w2[256 * 1024];

// ---------------- helpers ----------------
__device__ __forceinline__ uint32_t smem_u32(const void* p) {
    uint32_t a;
    asm("{ .reg .u64 t; cvta.to.shared.u64 t, %1; cvt.u32.u64 %0, t; }"
        : "=r"(a) : "l"(p));
    return a;
}
__device__ __forceinline__ float to_tf32(float x) {
    uint32_t u;
    asm("cvt.rna.tf32.f32 %0, %1;" : "=r"(u) : "f"(x));
    return __uint_as_float(u);
}
__device__ __forceinline__ void cp16(uint32_t dst, const float* src) {
    asm volatile("cp.async.ca.shared.global [%0], [%1], 16;" :: "r"(dst), "l"(src));
}
#define CP_COMMIT() asm volatile("cp.async.commit_group;" ::: "memory")
#define CP_WAIT(n)  asm volatile("cp.async.wait_group %0;" :: "n"(n) : "memory")

__device__ __forceinline__ void mma_tf32(float d[4], uint32_t a0, uint32_t a1,
                                         uint32_t a2, uint32_t a3,
                                         uint32_t b0, uint32_t b1) {
    asm volatile(
        "mma.sync.aligned.m16n8k8.row.col.f32.tf32.tf32.f32 "
        "{%0,%1,%2,%3}, {%4,%5,%6,%7}, {%8,%9}, {%0,%1,%2,%3};"
        : "+f"(d[0]), "+f"(d[1]), "+f"(d[2]), "+f"(d[3])
        : "r"(a0), "r"(a1), "r"(a2), "r"(a3), "r"(b0), "r"(b1));
}

// ---------------- CPE ----------------
__global__ void __launch_bounds__(256) cpe_kernel(
    const float* __restrict__ data, const int* __restrict__ neigh,
    const float* __restrict__ cpe_w, const float* __restrict__ bn_gamma,
    const float* __restrict__ bn_beta, const float* __restrict__ bn_mean,
    const float* __restrict__ bn_var)
{
    int n = blockIdx.x, c = threadIdx.x;
    __shared__ int nb[KC];
    if (c < KC) nb[c] = neigh[(size_t)n * KC + c];
    __syncthreads();
    float acc = 0.f;
    #pragma unroll
    for (int k = 0; k < KC; k++)
        acc = fmaf(data[(size_t)nb[k] * CDIM + c], cpe_w[k * CDIM + c], acc);
    float cpe = (acc - bn_mean[c]) * rsqrtf(bn_var[c] + EPS) * bn_gamma[c] + bn_beta[c];
    g_xpost[(size_t)n * CDIM + c] = data[(size_t)n * CDIM + c] + cpe;
}

// ---------------- weight transpose + tf32 round: dst[n*Kd+k] = src[k*Nd+n] ----
__global__ void transpose_w_kernel(const float* __restrict__ src,
                                   float* __restrict__ dst, int Kd, int Nd)
{
    int i = blockIdx.x * 256 + threadIdx.x;
    if (i < Kd * Nd) {
        int n = i / Kd, k = i - n * Kd;
        dst[i] = to_tf32(src[(size_t)k * Nd + n]);
    }
}

// ---------------- LN1 (build x) / LN2 ----------------
__global__ void __launch_bounds__(256) ln1_build_kernel(
    const float* __restrict__ relay, const float* __restrict__ g,
    const float* __restrict__ b)
{
    int warp = threadIdx.x >> 5, lane = threadIdx.x & 31;
    int gr = blockIdx.x * 8 + warp;
    int w = gr / SDIM, s = gr - w * SDIM;
    const float* src = (s == 0) ? (relay + (size_t)w * CDIM)
                                : (g_xpost + ((size_t)(w * KTOK + s - 1)) * CDIM);
    float v[8], sm = 0.f, s2 = 0.f;
    #pragma unroll
    for (int i = 0; i < 8; i++) {
        v[i] = src[lane + i * 32]; sm += v[i]; s2 = fmaf(v[i], v[i], s2);
    }
    #pragma unroll
    for (int o = 16; o; o >>= 1) {
        sm += __shfl_xor_sync(0xffffffffu, sm, o);
        s2 += __shfl_xor_sync(0xffffffffu, s2, o);
    }
    float mu = sm * (1.f / CDIM);
    float rs = rsqrtf(s2 * (1.f / CDIM) - mu * mu + EPS);
    #pragma unroll
    for (int i = 0; i < 8; i++) {
        int c = lane + i * 32;
        g_x[(size_t)gr * CDIM + c] = v[i];
        g_h[(size_t)gr * CDIM + c] = to_tf32((v[i] - mu) * rs * g[c] + b[c]);
    }
}

__global__ void __launch_bounds__(256) ln2_kernel(
    const float* __restrict__ g, const float* __restrict__ b)
{
    int warp = threadIdx.x >> 5, lane = threadIdx.x & 31;
    int gr = blockIdx.x * 8 + warp;
    const float* src = g_x2 + (size_t)gr * CDIM;
    float v[8], sm = 0.f, s2 = 0.f;
    #pragma unroll
    for (int i = 0; i < 8; i++) {
        v[i] = src[lane + i * 32]; sm += v[i]; s2 = fmaf(v[i], v[i], s2);
    }
    #pragma unroll
    for (int o = 16; o; o >>= 1) {
        sm += __shfl_xor_sync(0xffffffffu, sm, o);
        s2 += __shfl_xor_sync(0xffffffffu, s2, o);
    }
    float mu = sm * (1.f / CDIM);
    float rs = rsqrtf(s2 * (1.f / CDIM) - mu * mu + EPS);
    #pragma unroll
    for (int i = 0; i < 8; i++) {
        int c = lane + i * 32;
        g_h2[(size_t)gr * CDIM + c] = to_tf32((v[i] - mu) * rs * g[c] + b[c]);
    }
}

// ---------------- attention (fp32, per window) ----------------
#define AST 772
__global__ void __launch_bounds__(288) attn_kernel()
{
    extern __shared__ float sq[];   // [33][772]
    int w = blockIdx.x, tid = threadIdx.x;
    const float* src = g_qkv + (size_t)w * SDIM * 768;
    for (int i = tid; i < SDIM * 192; i += 288) {
        int r = i / 192, c = i - r * 192;
        *reinterpret_cast<float4*>(sq + r * AST + c * 4) =
            *reinterpret_cast<const float4*>(src + r * 768 + c * 4);
    }
    __syncthreads();
    if (tid < HEADS * SDIM) {
        int h = tid / SDIM, s = tid - h * SDIM;
        const float scale = 0.17677669529663687f;
        float q[DHEAD];
        #pragma unroll
        for (int d = 0; d < DHEAD; d++) q[d] = sq[s * AST + h * DHEAD + d] * scale;
        float sc[SDIM], mx = -1e30f;
        #pragma unroll 1
        for (int t = 0; t < SDIM; t++) {
            const float* kr = sq + t * AST + 256 + h * DHEAD;
            float dot = 0.f;
            #pragma unroll
            for (int d = 0; d < DHEAD; d++) dot = fmaf(q[d], kr[d], dot);
            sc[t] = dot; mx = fmaxf(mx, dot);
        }
        float ssum = 0.f;
        #pragma unroll
        for (int t = 0; t < SDIM; t++) { sc[t] = expf(sc[t] - mx); ssum += sc[t]; }
        float inv = 1.f / ssum;
        float o[DHEAD];
        #pragma unroll
        for (int d = 0; d < DHEAD; d++) o[d] = 0.f;
        #pragma unroll 1
        for (int t = 0; t < SDIM; t++) {
            const float* vr = sq + t * AST + 512 + h * DHEAD;
            float p = sc[t] * inv;
            #pragma unroll
            for (int d = 0; d < DHEAD; d++) o[d] = fmaf(p, vr[d], o[d]);
        }
        float* dst = g_attn + ((size_t)w * SDIM + s) * CDIM + h * DHEAD;
        #pragma unroll
        for (int d = 0; d < DHEAD; d++) dst[d] = to_tf32(o[d]);
    }
}

// ---------------- tf32 mma.sync GEMM ----------------
// D[128,128 tile] = A[m0:m0+128, :KT] @ B[n0:n0+128, :KT]^T
// A: [RTOT, KT] activations (tf32-rounded), B: [NT, KT] weights (tf32-rounded)
// EPI: 0 = +bias   1 = +bias+res   2 = +bias,gelu   3 = +bias+res,scatter-out
#define CHUNK_K 32
#define ASTR    36                   /* padded floats per smem row */
#define BUF_FLT (128 * ASTR * 2)     /* A + B per buffer = 9216 floats */
#define GEMM_SMEM (2 * BUF_FLT * 4)  /* 73728 bytes */

template<int KT, int NT, int EPI>
__global__ void __launch_bounds__(256) gemm_mma(
    const float* __restrict__ A, const float* __restrict__ B,
    const float* __restrict__ bias, const float* __restrict__ res,
    float* __restrict__ outp)
{
    extern __shared__ float smem[];
    const int tid = threadIdx.x;
    const int wid = tid >> 5, lane = tid & 31;
    const int g = lane >> 2, t = lane & 3;
    const int warp_m = wid & 1, warp_n = wid >> 1;   // 2 x 4 warp grid, 64x32 tiles
    const int m0 = blockIdx.x * 128;
    const int n0 = blockIdx.y * 128;
    const uint32_t sbase = smem_u32(smem);

    float acc[4][4][4];
    #pragma unroll
    for (int i = 0; i < 4; i++)
        #pragma unroll
        for (int j = 0; j < 4; j++)
            #pragma unroll
            for (int r = 0; r < 4; r++) acc[i][j][r] = 0.f;

    constexpr int KCH = KT / CHUNK_K;

    // --- async loader for one K-chunk into buffer s ---
    auto load_chunk = [&](int s, int kc) {
        uint32_t base = sbase + (uint32_t)s * BUF_FLT * 4;
        #pragma unroll
        for (int it = 0; it < 4; it++) {
            int idx = it * 256 + tid;
            int row = idx >> 3, seg = idx & 7;
            cp16(base + (uint32_t)(row * ASTR + seg * 4) * 4,
                 A + (size_t)(m0 + row) * KT + kc * CHUNK_K + seg * 4);
        }
        #pragma unroll
        for (int it = 0; it < 4; it++) {
            int idx = it * 256 + tid;
            int row = idx >> 3, seg = idx & 7;
            cp16(base + (uint32_t)(128 * ASTR + row * ASTR + seg * 4) * 4,
                 B + (size_t)(n0 + row) * KT + kc * CHUNK_K + seg * 4);
        }
    };

    load_chunk(0, 0); CP_COMMIT();

    for (int kc = 0; kc < KCH; kc++) {
        int s = kc & 1;
        if (kc + 1 < KCH) {
            load_chunk((kc + 1) & 1, kc + 1); CP_COMMIT();
            CP_WAIT(1);
        } else {
            CP_WAIT(0);
        }
        __syncthreads();

        const float* Asm = smem + s * BUF_FLT;
        const float* Bsm = Asm + 128 * ASTR;

        #pragma unroll
        for (int ks = 0; ks < 4; ks++) {
            uint32_t bf[4][2];
            #pragma unroll
            for (int nt = 0; nt < 4; nt++) {
                int col = warp_n * 32 + nt * 8 + g;
                bf[nt][0] = __float_as_uint(Bsm[col * ASTR + ks * 8 + t]);
                bf[nt][1] = __float_as_uint(Bsm[col * ASTR + ks * 8 + t + 4]);
            }
            #pragma unroll
            for (int mt = 0; mt < 4; mt++) {
                int row = warp_m * 64 + mt * 16 + g;
                uint32_t a0 = __float_as_uint(Asm[row * ASTR + ks * 8 + t]);
                uint32_t a1 = __float_as_uint(Asm[(row + 8) * ASTR + ks * 8 + t]);
                uint32_t a2 = __float_as_uint(Asm[row * ASTR + ks * 8 + t + 4]);
                uint32_t a3 = __float_as_uint(Asm[(row + 8) * ASTR + ks * 8 + t + 4]);
                #pragma unroll
                for (int nt = 0; nt < 4; nt++)
                    mma_tf32(acc[mt][nt], a0, a1, a2, a3, bf[nt][0], bf[nt][1]);
            }
        }
        __syncthreads();
    }

    // --- epilogue: fragments -> smem (stride 132) -> coalesced global ---
    float* stg = smem;
    #pragma unroll
    for (int mt = 0; mt < 4; mt++) {
        #pragma unroll
        for (int nt = 0; nt < 4; nt++) {
            int row = warp_m * 64 + mt * 16 + g;
            int col = warp_n * 32 + nt * 8 + 2 * t;
            stg[row * 132 + col]           = acc[mt][nt][0];
            stg[row * 132 + col + 1]       = acc[mt][nt][1];
            stg[(row + 8) * 132 + col]     = acc[mt][nt][2];
            stg[(row + 8) * 132 + col + 1] = acc[mt][nt][3];
        }
    }
    __syncthreads();

    int col = tid & 127;
    int r0  = tid >> 7;               // 0 or 1
    float bi = bias[n0 + col];
    #pragma unroll 4
    for (int i = 0; i < 64; i++) {
        int r = r0 + i * 2;
        int gr = m0 + r;
        float v = stg[r * 132 + col] + bi;
        if (EPI == 1 || EPI == 3) v += res[(size_t)gr * NT + n0 + col];
        if (EPI == 2) {
            float x3 = v * v * v;
            float th = tanhf(0.7978845608028654f * (v + 0.044715f * x3));
            v = to_tf32(0.5f * v * (1.f + th));
        }
        if (EPI == 3) {
            int w = gr / SDIM, s = gr - (gr / SDIM) * SDIM;
            size_t dst = (s == 0)
                ? ((size_t)NTOK * CDIM + (size_t)w * CDIM + n0 + col)
                : (((size_t)(w * KTOK + s - 1)) * CDIM + n0 + col);
            outp[dst] = v;
        } else {
            outp[(size_t)gr * NT + n0 + col] = v;
        }
    }
}

// ---------------------------------------------------------------------------
extern "C" void kernel_launch(void* const* d_in, const int* in_sizes, int n_in,
                              void* d_out, int out_size)
{
    const float* data     = (const float*)d_in[0];
    const float* relay    = (const float*)d_in[1];
    const int*   neigh    = (const int*)  d_in[2];
    const float* cpe_w    = (const float*)d_in[3];
    const float* bn_gamma = (const float*)d_in[4];
    const float* bn_beta  = (const float*)d_in[5];
    const float* bn_mean  = (const float*)d_in[6];
    const float* bn_var   = (const float*)d_in[7];
    const float* norm1_g  = (const float*)d_in[8];
    const float* norm1_b  = (const float*)d_in[9];
    const float* qkv_w    = (const float*)d_in[10];
    const float* qkv_b    = (const float*)d_in[11];
    const float* proj_w   = (const float*)d_in[12];
    const float* proj_b   = (const float*)d_in[13];
    const float* norm2_g  = (const float*)d_in[14];
    const float* norm2_b  = (const float*)d_in[15];
    const float* fc1_w    = (const float*)d_in[16];
    const float* fc1_b    = (const float*)d_in[17];
    const float* fc2_w    = (const float*)d_in[18];
    const float* fc2_b    = (const float*)d_in[19];
    float* out = (float*)d_out;

    const int ATTN_SMEM = SDIM * AST * 4;

    static bool inited = false;
    static float *p_h, *p_h2, *p_qkv, *p_attn, *p_f1, *p_x, *p_x2;
    static float *p_wq, *p_wp, *p_w1, *p_w2;
    if (!inited) {
        cudaFuncSetAttribute(gemm_mma<256, 768, 0>,
            cudaFuncAttributeMaxDynamicSharedMemorySize, GEMM_SMEM);
        cudaFuncSetAttribute(gemm_mma<256, 256, 1>,
            cudaFuncAttributeMaxDynamicSharedMemorySize, GEMM_SMEM);
        cudaFuncSetAttribute(gemm_mma<256, 1024, 2>,
            cudaFuncAttributeMaxDynamicSharedMemorySize, GEMM_SMEM);
        cudaFuncSetAttribute(gemm_mma<1024, 256, 3>,
            cudaFuncAttributeMaxDynamicSharedMemorySize, GEMM_SMEM);
        cudaFuncSetAttribute(attn_kernel,
            cudaFuncAttributeMaxDynamicSharedMemorySize, ATTN_SMEM);
        void* t;
        cudaGetSymbolAddress(&t, g_h);    p_h    = (float*)t;
        cudaGetSymbolAddress(&t, g_h2);   p_h2   = (float*)t;
        cudaGetSymbolAddress(&t, g_qkv);  p_qkv  = (float*)t;
        cudaGetSymbolAddress(&t, g_attn); p_attn = (float*)t;
        cudaGetSymbolAddress(&t, g_f1);   p_f1   = (float*)t;
        cudaGetSymbolAddress(&t, g_x);    p_x    = (float*)t;
        cudaGetSymbolAddress(&t, g_x2);   p_x2   = (float*)t;
        cudaGetSymbolAddress(&t, g_wq);   p_wq   = (float*)t;
        cudaGetSymbolAddress(&t, g_wp);   p_wp   = (float*)t;
        cudaGetSymbolAddress(&t, g_w1);   p_w1   = (float*)t;
        cudaGetSymbolAddress(&t, g_w2);   p_w2   = (float*)t;
        inited = true;
    }

    cpe_kernel<<<NTOK, 256>>>(data, neigh, cpe_w, bn_gamma, bn_beta, bn_mean, bn_var);

    transpose_w_kernel<<<(768 * 256 + 255) / 256, 256>>>(qkv_w,  p_wq, 256, 768);
    transpose_w_kernel<<<(256 * 256 + 255) / 256, 256>>>(proj_w, p_wp, 256, 256);
    transpose_w_kernel<<<(1024 * 256 + 255) / 256, 256>>>(fc1_w, p_w1, 256, 1024);
    transpose_w_kernel<<<(256 * 1024 + 255) / 256, 256>>>(fc2_w, p_w2, 1024, 256);

    ln1_build_kernel<<<RTOT / 8, 256>>>(relay, norm1_g, norm1_b);

    const int GB = RTOT / 128;  // 1056
    gemm_mma<256, 768, 0><<<dim3(GB, 6), 256, GEMM_SMEM>>>(p_h, p_wq, qkv_b, nullptr, p_qkv);

    attn_kernel<<<W_WIN, 288, ATTN_SMEM>>>();

    gemm_mma<256, 256, 1><<<dim3(GB, 2), 256, GEMM_SMEM>>>(p_attn, p_wp, proj_b, p_x, p_x2);

    ln2_kernel<<<RTOT / 8, 256>>>(norm2_g, norm2_b);

    gemm_mma<256, 1024, 2><<<dim3(GB, 8), 256, GEMM_SMEM>>>(p_h2, p_w1, fc1_b, nullptr, p_f1);

    gemm_mma<1024, 256, 3><<<dim3(GB, 2), 256, GEMM_SMEM>>>(p_f1, p_w2, fc2_b, p_x2, out);
}